// round 11
// baseline (speedup 1.0000x reference)
#include <cuda_runtime.h>
#include <stdint.h>
#include <math.h>

// Problem constants (fixed shapes: scores (128, 4096, 2))
#define NN   4096
#define BSZ  128
#define ENS  2
#define BE   256           // BSZ*ENS
#define KK   32
#define NEGC (-1e30f)
#define HALF_OUT 1048576   // 128*4096*2
#define NCHUNK 32
#define CLEN   128         // NN / NCHUNK
#define NSLICE 8
#define SLEN   512         // NN / NSLICE
#define BK_BLK 16          // backward blocks: 16 groups of 8 lanes each = 256 b

// ---------------- scratch (static device memory) ----------------
__device__ float    g_B[(size_t)(NN + 1) * BE * KK]; // B[i][b][j-1]
__device__ float    g_F[(size_t)NN * BE * KK];       // F[i][b][j] (pre-update)
__device__ unsigned g_mask[(size_t)BE * NN];         // inclusion masks [b*NN + i]
__device__ float    g_CE[(size_t)BE * NCHUNK * KK];  // chunk ESPs
__device__ float    g_BD[(size_t)BE * NCHUNK * KK];  // chunk boundary prefixes
__device__ float    g_S[(size_t)NN * BE];            // th + log_ekm1 (unnormalized)
__device__ float    g_T[(size_t)NN * BE];            // transposed theta [i*BE + b]
__device__ float    g_E[(size_t)BE * KK];            // backward state between slices
__device__ float    g_logZ[BE];
__device__ unsigned g_bits[(size_t)BE * (NN / 32)];  // sampled bits
// sampler chunk-function tables: per (b, chunk c of 128, r_in=lane+1)
__device__ unsigned g_sampBits[(size_t)BE * 128 * 32];
__device__ unsigned g_sampMap[(size_t)BE * 128 * 32];

// ---------------- threefry2x32, key = (0, 42) ----------------
__device__ __forceinline__ uint32_t tf_bits(uint32_t lo)
{
    uint32_t x0 = 0u;
    uint32_t x1 = lo;
    const uint32_t ks0 = 0u, ks1 = 42u, ks2 = 0x1BD11BF0u;
    x0 += ks0; x1 += ks1;
#define TFR(r) { x0 += x1; x1 = (x1 << (r)) | (x1 >> (32 - (r))); x1 ^= x0; }
    TFR(13) TFR(15) TFR(26) TFR(6)   x0 += ks1; x1 += ks2 + 1u;
    TFR(17) TFR(29) TFR(16) TFR(24)  x0 += ks2; x1 += ks0 + 2u;
    TFR(13) TFR(15) TFR(26) TFR(6)   x0 += ks0; x1 += ks1 + 3u;
    TFR(17) TFR(29) TFR(16) TFR(24)  x0 += ks1; x1 += ks2 + 4u;
    TFR(13) TFR(15) TFR(26) TFR(6)   x0 += ks2; x1 += ks0 + 5u;
#undef TFR
    return x0 ^ x1;
}

// EXACT logaddexp (libdevice — bitwise path for sampling masks)
__device__ __forceinline__ float logaddexpf32(float x, float y)
{
    float d = x - y;
    return fmaxf(x, y) + log1pf(expf(-fabsf(d)));
}

// Fast logaddexp (marginals path, 1e-3 tolerance)
__device__ __forceinline__ float logaddexp_fast(float x, float y)
{
    float d = x - y;
    return fmaxf(x, y) + __logf(1.0f + __expf(-fabsf(d)));
}

// ---------------- backward slice: 8 lanes x 4 ESP-slots per b ----------------
// Per (i,j) arithmetic is bit-identical to the 32-lane version; only the
// register layout changed. 4 independent exact logaddexps per lane per step
// pipeline, so the critical path is ~(4 LAE + 1 shfl)/4 per step.
__device__ void backward_slice(const float* __restrict__ scores, int s)
{
    const unsigned FULL = 0xffffffffu;
    int subl = threadIdx.x & 7;
    int b = blockIdx.x * 16 + (threadIdx.x >> 3);
    const int bz = b >> 1, e = b & 1;
    const float* thbase = scores + (size_t)bz * (NN * ENS) + e;

    float E0, E1, E2, E3;   // slots j = 4*subl + {1,2,3,4} (log e_j)
    if (s == 0) {
        E0 = E1 = E2 = E3 = NEGC;
        *(float4*)&g_B[((size_t)NN * BE + b) * KK + subl * 4] =
            make_float4(NEGC, NEGC, NEGC, NEGC);   // init row (i = NN)
    } else {
        float4 v = *(const float4*)&g_E[(size_t)b * KK + subl * 4];
        E0 = v.x; E1 = v.y; E2 = v.z; E3 = v.w;
    }

    int blk_hi = (NN / 32) - 16 * s;        // exclusive
    int blk_lo = blk_hi - 16;

    float th0, th1, th2, th3;               // theta for i = base + subl*4 + {0..3}
    {
        int i0 = (blk_hi - 1) * 32 + subl * 4;
        th0 = thbase[2*(i0+0)]; th1 = thbase[2*(i0+1)];
        th2 = thbase[2*(i0+2)]; th3 = thbase[2*(i0+3)];
    }

    for (int blk = blk_hi - 1; blk >= blk_lo; --blk) {
        int base = blk * 32;
        float tn0 = 0.f, tn1 = 0.f, tn2 = 0.f, tn3 = 0.f;
        if (blk > blk_lo) {                 // prefetch next block's theta
            int i0 = (blk - 1) * 32 + subl * 4;
            tn0 = thbase[2*(i0+0)]; tn1 = thbase[2*(i0+1)];
            tn2 = thbase[2*(i0+2)]; tn3 = thbase[2*(i0+3)];
        }
        // uniforms for this lane's 4 i's (bit-identical index i*BE+b)
        float uv0, uv1, uv2, uv3;
        {
            int i0 = base + subl * 4;
            uint32_t r0 = tf_bits((uint32_t)((i0+0) * BE + b));
            uint32_t r1 = tf_bits((uint32_t)((i0+1) * BE + b));
            uint32_t r2 = tf_bits((uint32_t)((i0+2) * BE + b));
            uint32_t r3 = tf_bits((uint32_t)((i0+3) * BE + b));
            uv0 = fmaxf(__uint_as_float((r0 >> 9) | 0x3f800000u) - 1.0f, 0.0f);
            uv1 = fmaxf(__uint_as_float((r1 >> 9) | 0x3f800000u) - 1.0f, 0.0f);
            uv2 = fmaxf(__uint_as_float((r2 >> 9) | 0x3f800000u) - 1.0f, 0.0f);
            uv3 = fmaxf(__uint_as_float((r3 >> 9) | 0x3f800000u) - 1.0f, 0.0f);
        }

#pragma unroll
        for (int g8 = 3; g8 >= 0; --g8) {
            float lq0[8], lq1[8], lq2[8], lq3[8];
            // chain segment: 8 exact steps (4 independent LAEs each)
#pragma unroll
            for (int t = 7; t >= 0; --t) {
                int ii = g8 * 8 + t;
                float tsel = (ii & 2) ? ((ii & 1) ? th3 : th2) : ((ii & 1) ? th1 : th0);
                float thi = __shfl_sync(FULL, tsel, ii >> 2, 8);
                float top = __shfl_up_sync(FULL, E3, 1, 8);
                float p = (subl == 0) ? 0.0f : top;      // e_0 boundary (log e_0 = 0)
                float s3 = E2 + thi; float n3 = logaddexpf32(E3, s3); lq3[t] = s3 - n3;
                float s2 = E1 + thi; float n2 = logaddexpf32(E2, s2); lq2[t] = s2 - n2;
                float s1 = E0 + thi; float n1 = logaddexpf32(E1, s1); lq1[t] = s1 - n1;
                float s0 = p  + thi; float n0 = logaddexpf32(E0, s0); lq0[t] = s0 - n0;
                E0 = n0; E1 = n1; E2 = n2; E3 = n3;
                *(float4*)&g_B[((size_t)(base + ii) * BE + b) * KK + subl * 4] =
                    make_float4(n0, n1, n2, n3);
            }
            // deferred mask generation (off critical path, bit-exact assembly)
#pragma unroll
            for (int t = 7; t >= 0; --t) {
                int ii = g8 * 8 + t;
                float usel = (ii & 2) ? ((ii & 1) ? uv3 : uv2) : ((ii & 1) ? uv1 : uv0);
                float u = __shfl_sync(FULL, usel, ii >> 2, 8);
                unsigned bits =
                    ((u < expf(fminf(lq0[t], 0.0f))) ? 1u : 0u) |
                    ((u < expf(fminf(lq1[t], 0.0f))) ? 2u : 0u) |
                    ((u < expf(fminf(lq2[t], 0.0f))) ? 4u : 0u) |
                    ((u < expf(fminf(lq3[t], 0.0f))) ? 8u : 0u);
                unsigned w = bits << (subl * 4);
                w |= __shfl_xor_sync(FULL, w, 1, 8);
                w |= __shfl_xor_sync(FULL, w, 2, 8);
                w |= __shfl_xor_sync(FULL, w, 4, 8);
                if (subl == 0) g_mask[(size_t)b * NN + base + ii] = w;
            }
        }
        th0 = tn0; th1 = tn1; th2 = tn2; th3 = tn3;
    }

    if (s < NSLICE - 1) {
        *(float4*)&g_E[(size_t)b * KK + subl * 4] = make_float4(E0, E1, E2, E3);
    } else {
        float lz = __shfl_sync(FULL, E3, 7, 8);   // j=32: slot 3 of sub-lane 7 = logZ
        if (subl == 0) g_logZ[b] = lz;
    }
}

// ---------------- sampler chunk-function evaluation ----------------
__device__ void samp_chunk(int xb, int band)
{
    int lane = threadIdx.x & 31;
    int item = xb * 4 + (threadIdx.x >> 5);   // 0..4095
    int b = item >> 4;
    int c = (112 - 16 * band) + (item & 15);  // chunk index 0..127

    unsigned mv = g_mask[(size_t)b * NN + c * 32 + lane];  // coalesced
    unsigned r = (unsigned)(lane + 1);
    unsigned w = 0u;
#pragma unroll
    for (int ii = 0; ii < 32; ++ii) {
        unsigned m = __shfl_sync(0xffffffffu, mv, ii);
        unsigned incl = r ? ((m >> (r - 1u)) & 1u) : 0u;
        r -= incl;
        w |= incl << ii;
    }
    g_sampBits[((size_t)b * 128 + c) * 32 + lane] = w;
    g_sampMap[((size_t)b * 128 + c) * 32 + lane] = r;
}

// ---------------- sampler composition: thread the real state ----------------
__global__ void k_comp()
{
    int lane = threadIdx.x & 31;
    int b = blockIdx.x * 4 + (threadIdx.x >> 5);
    const unsigned* mp = &g_sampMap[(size_t)b * 128 * 32];
    const unsigned* bp = &g_sampBits[(size_t)b * 128 * 32];

    unsigned r = KK;   // warp-uniform
#pragma unroll 4
    for (int c = 0; c < 128; ++c) {
        unsigned mapv = mp[c * 32 + lane];   // loads independent of r (pipelined)
        unsigned bitv = bp[c * 32 + lane];
        unsigned idx = r ? (r - 1u) : 0u;
        unsigned bits = __shfl_sync(0xffffffffu, bitv, idx);
        unsigned rn   = __shfl_sync(0xffffffffu, mapv, idx);
        if (!r) { bits = 0u; rn = 0u; }
        if (lane == 0) g_bits[(size_t)b * 128 + c] = bits;
        r = rn;
    }
}

// ---------------- worker pieces (unchanged numerics) ----------------
__device__ void phaseA(const float* __restrict__ scores, int xb)
{
    int lane = threadIdx.x & 31;
    int wid = xb * 4 + (threadIdx.x >> 5);   // 0..8191
    int b = wid >> 5;
    int c = wid & 31;
    const int bz = b >> 1, e = b & 1;
    const float* thbase = scores + (size_t)bz * (NN * ENS) + e;

    float F = (lane == 0) ? 0.0f : NEGC;
    int base0 = c * CLEN;
    for (int blk = 0; blk < CLEN / 32; ++blk) {
        float thv = thbase[2 * (base0 + blk * 32 + lane)];
#pragma unroll 8
        for (int ii = 0; ii < 32; ++ii) {
            float th = __shfl_sync(0xffffffffu, thv, ii);
            float Fp = __shfl_up_sync(0xffffffffu, F, 1);
            if (lane == 0) Fp = NEGC;
            F = logaddexp_fast(F, Fp + th);
        }
    }
    g_CE[((size_t)b * NCHUNK + c) * KK + lane] = F;
}

__device__ void transpose_theta(const float* __restrict__ scores, int xb)
{
    int idx = (xb * 128 + threadIdx.x) * 4;
#pragma unroll
    for (int q = 0; q < 4; ++q, ++idx) {
        int b = idx & (BE - 1);
        int i = idx >> 8;
        g_T[idx] = scores[(size_t)(b >> 1) * (NN * ENS) + i * ENS + (b & 1)];
    }
}

__device__ void merge_chunks(int xb)
{
    int lane = threadIdx.x & 31;
    int b = xb * 4 + (threadIdx.x >> 5);

    float P = (lane == 0) ? 0.0f : NEGC;
    for (int c = 0; c < NCHUNK; ++c) {
        g_BD[((size_t)b * NCHUNK + c) * KK + lane] = P;  // exclusive prefix
        float L = g_CE[((size_t)b * NCHUNK + c) * KK + lane];
        float mx = NEGC;
#pragma unroll
        for (int m = 0; m < 32; ++m) {
            float Pm = __shfl_sync(0xffffffffu, P, m);
            float Lx = __shfl_sync(0xffffffffu, L, (lane - m) & 31);
            if (m <= lane) mx = fmaxf(mx, Pm + Lx);
        }
        float sum = 0.0f;
#pragma unroll
        for (int m = 0; m < 32; ++m) {
            float Pm = __shfl_sync(0xffffffffu, P, m);
            float Lx = __shfl_sync(0xffffffffu, L, (lane - m) & 31);
            if (m <= lane) sum += __expf(Pm + Lx - mx);
        }
        P = mx + __logf(sum);
    }
}

__device__ void phaseC_storeF(const float* __restrict__ scores, int xb)
{
    int lane = threadIdx.x & 31;
    int wid = xb * 4 + (threadIdx.x >> 5);
    int b = wid >> 5;
    int c = wid & 31;
    const int bz = b >> 1, e = b & 1;
    const float* thbase = scores + (size_t)bz * (NN * ENS) + e;

    float F = g_BD[((size_t)b * NCHUNK + c) * KK + lane];
    int base0 = c * CLEN;
    for (int blk = 0; blk < CLEN / 32; ++blk) {
        float thv = thbase[2 * (base0 + blk * 32 + lane)];
#pragma unroll 8
        for (int ii = 0; ii < 32; ++ii) {
            int i = base0 + blk * 32 + ii;
            g_F[((size_t)i * BE + b) * KK + lane] = F;
            float th = __shfl_sync(0xffffffffu, thv, ii);
            float Fp = __shfl_up_sync(0xffffffffu, F, 1);
            if (lane == 0) Fp = NEGC;
            F = logaddexp_fast(F, Fp + th);
        }
    }
}

__device__ void comb_band(int xb, int rowbase)
{
    int tid = xb * 128 + threadIdx.x;
    int b = tid & (BE - 1);
    int i = rowbase + (tid >> 8);

    const float4* Fr = reinterpret_cast<const float4*>(&g_F[((size_t)i * BE + b) * KK]);
    const float4* Br = reinterpret_cast<const float4*>(&g_B[((size_t)(i + 1) * BE + b) * KK]);

    float Fv[32], Bv[32];
#pragma unroll
    for (int q = 0; q < 8; ++q) {
        float4 f4 = Fr[q];
        Fv[4 * q + 0] = f4.x; Fv[4 * q + 1] = f4.y; Fv[4 * q + 2] = f4.z; Fv[4 * q + 3] = f4.w;
        float4 b4 = Br[q];
        Bv[4 * q + 0] = b4.x; Bv[4 * q + 1] = b4.y; Bv[4 * q + 2] = b4.z; Bv[4 * q + 3] = b4.w;
    }

    float comb[32];
#pragma unroll
    for (int j = 0; j < 32; ++j) {
        float bc = (j == 31) ? 0.0f : Bv[30 - j];   // B[i+1][31-j]; col 0 == 0
        comb[j] = Fv[j] + bc;
    }
    float mx = comb[0];
#pragma unroll
    for (int j = 1; j < 32; ++j) mx = fmaxf(mx, comb[j]);
    float sum = 0.0f;
#pragma unroll
    for (int j = 0; j < 32; ++j) sum += __expf(comb[j] - mx);

    g_S[(size_t)i * BE + b] = g_T[(size_t)i * BE + b] + mx + __logf(sum);
}

// ---------------- sliced fused kernel ----------------
__global__ void k_slice(const float* __restrict__ scores, int s)
{
    if (blockIdx.x < BK_BLK) {
        backward_slice(scores, s);
        return;
    }
    int xb = blockIdx.x - BK_BLK;
    if (s == 0) {
        if (xb < 2048) phaseA(scores, xb);
        else transpose_theta(scores, xb - 2048);
    } else if (s == 1) {
        if (xb < 64) merge_chunks(xb);
        else samp_chunk(xb - 64, 0);
    } else if (s == 2) {
        if (xb < 2048) phaseC_storeF(scores, xb);
        else samp_chunk(xb - 2048, 1);
    } else if (s == 3) {
        if (xb < 3072) comb_band(xb, 2560);          // rows [2560,4096)
        else samp_chunk(xb - 3072, 2);
    } else {
        // s=4..7: comb rows [4096-512s, 4096-512(s-1)) + sampler chunks band s-1
        if (xb < 1024) comb_band(xb, NN - SLEN * s);
        else samp_chunk(xb - 1024, s - 1);
    }
}

// ---------------- tail: last comb band + last sampler chunk band ----------------
__global__ void k_tail()
{
    if (blockIdx.x < 1024) comb_band(blockIdx.x, 0);   // rows [0, 512)
    else samp_chunk(blockIdx.x - 1024, 7);             // chunks [0,16)
}

// ---------------- finalize ----------------
__global__ void k_final(float* __restrict__ out)
{
    int tid = blockIdx.x * blockDim.x + threadIdx.x;  // 0 .. 2^20-1
    int bz = tid >> 13;
    int rem = tid & 8191;
    int n = rem >> 1;
    int e = rem & 1;
    int be = bz * ENS + e;
    float s = (float)((g_bits[(size_t)be * (NN / 32) + (n >> 5)] >> (n & 31)) & 1u);
    float m = __expf(g_S[(size_t)n * BE + be] - g_logZ[be]);
    out[tid] = (s - m) + m;
    out[HALF_OUT + tid] = m;
}

extern "C" void kernel_launch(void* const* d_in, const int* in_sizes, int n_in,
                              void* d_out, int out_size)
{
    const float* scores = (const float*)d_in[0];
    float* out = (float*)d_out;
    (void)in_sizes; (void)n_in; (void)out_size;

    k_slice<<<BK_BLK + 2048 + 2048, 128>>>(scores, 0);  // backward + phaseA + transpose
    k_slice<<<BK_BLK + 64 + 1024,   128>>>(scores, 1);  // backward + merge + sc b0
    k_slice<<<BK_BLK + 2048 + 1024, 128>>>(scores, 2);  // backward + phaseC + sc b1
    k_slice<<<BK_BLK + 3072 + 1024, 128>>>(scores, 3);  // backward + comb + sc b2
    k_slice<<<BK_BLK + 1024 + 1024, 128>>>(scores, 4);  // backward + comb + sc b3
    k_slice<<<BK_BLK + 1024 + 1024, 128>>>(scores, 5);  // backward + comb + sc b4
    k_slice<<<BK_BLK + 1024 + 1024, 128>>>(scores, 6);  // backward + comb + sc b5
    k_slice<<<BK_BLK + 1024 + 1024, 128>>>(scores, 7);  // backward + comb + sc b6
    k_tail<<<2048, 128>>>();                            // comb [0,512) + sc band7
    k_comp<<<64, 128>>>();                              // sampler composition
    k_final<<<2048, 512>>>(out);
}

// round 12
// speedup vs baseline: 2.4889x; 2.4889x over previous
#include <cuda_runtime.h>
#include <stdint.h>
#include <math.h>

// Problem constants (fixed shapes: scores (128, 4096, 2))
#define NN   4096
#define BSZ  128
#define ENS  2
#define BE   256           // BSZ*ENS
#define KK   32
#define NEGC (-1e30f)
#define HALF_OUT 1048576   // 128*4096*2
#define NCHUNK 32
#define CLEN   128         // NN / NCHUNK
#define NSLICE 8
#define SLEN   512         // NN / NSLICE

// ---------------- scratch (static device memory) ----------------
__device__ float    g_B[(size_t)(NN + 1) * BE * KK]; // B[i][b][j-1]
__device__ float    g_F[(size_t)NN * BE * KK];       // F[i][b][j] (pre-update)
__device__ unsigned g_mask[(size_t)BE * NN];         // inclusion masks [b*NN + i]
__device__ float    g_CE[(size_t)BE * NCHUNK * KK];  // chunk ESPs
__device__ float    g_BD[(size_t)BE * NCHUNK * KK];  // chunk boundary prefixes
__device__ float    g_S[(size_t)NN * BE];            // th + log_ekm1 (unnormalized)
__device__ float    g_T[(size_t)NN * BE];            // transposed theta [i*BE + b]
__device__ float    g_E[(size_t)BE * KK];            // backward state between slices
__device__ float    g_logZ[BE];
__device__ unsigned g_bits[(size_t)BE * (NN / 32)];  // sampled bits
// sampler chunk-function tables: per (b, chunk c, r_in=lane+1); chunks 16..127 only
__device__ unsigned g_sampBits[(size_t)BE * 128 * 32];
__device__ unsigned g_sampMap[(size_t)BE * 128 * 32];

// ---------------- threefry2x32, key = (0, 42) ----------------
__device__ __forceinline__ uint32_t tf_bits(uint32_t lo)
{
    uint32_t x0 = 0u;
    uint32_t x1 = lo;
    const uint32_t ks0 = 0u, ks1 = 42u, ks2 = 0x1BD11BF0u;
    x0 += ks0; x1 += ks1;
#define TFR(r) { x0 += x1; x1 = (x1 << (r)) | (x1 >> (32 - (r))); x1 ^= x0; }
    TFR(13) TFR(15) TFR(26) TFR(6)   x0 += ks1; x1 += ks2 + 1u;
    TFR(17) TFR(29) TFR(16) TFR(24)  x0 += ks2; x1 += ks0 + 2u;
    TFR(13) TFR(15) TFR(26) TFR(6)   x0 += ks0; x1 += ks1 + 3u;
    TFR(17) TFR(29) TFR(16) TFR(24)  x0 += ks1; x1 += ks2 + 4u;
    TFR(13) TFR(15) TFR(26) TFR(6)   x0 += ks2; x1 += ks0 + 5u;
#undef TFR
    return x0 ^ x1;
}

// EXACT logaddexp (libdevice — bitwise path for sampling masks)
__device__ __forceinline__ float logaddexpf32(float x, float y)
{
    float d = x - y;
    return fmaxf(x, y) + log1pf(expf(-fabsf(d)));
}

// Fast logaddexp (marginals path, 1e-3 tolerance)
__device__ __forceinline__ float logaddexp_fast(float x, float y)
{
    float d = x - y;
    return fmaxf(x, y) + __logf(1.0f + __expf(-fabsf(d)));
}

// ---------------- backward slice (exact chain, DEFERRED ballots) ----------------
__device__ void backward_slice(const float* __restrict__ scores, int s)
{
    int lane = threadIdx.x & 31;
    int b = blockIdx.x * 4 + (threadIdx.x >> 5);
    const int bz = b >> 1, e = b & 1;
    const float* thbase = scores + (size_t)bz * (NN * ENS) + e;

    float E;
    if (s == 0) {
        E = NEGC;
        g_B[((size_t)NN * BE + b) * KK + lane] = NEGC;   // init row (i = NN)
    } else {
        E = g_E[(size_t)b * KK + lane];
    }

    int blk_hi = (NN / 32) - 16 * s;        // exclusive
    int blk_lo = blk_hi - 16;

    // prefetch theta for the first block of this slice
    float thv = thbase[2 * ((blk_hi - 1) * 32 + lane)];

    for (int blk = blk_hi - 1; blk >= blk_lo; --blk) {
        int base = blk * 32;
        float thv_next = (blk > blk_lo) ? thbase[2 * ((blk - 1) * 32 + lane)] : 0.0f;
        // inline threefry uniform (bit-identical to jax.random.uniform, index i*BE+b)
        uint32_t rb = tf_bits((uint32_t)((base + lane) * BE + b));
        float uv = fmaxf(__uint_as_float((rb >> 9) | 0x3f800000u) - 1.0f, 0.0f);

#pragma unroll
        for (int g8 = 3; g8 >= 0; --g8) {
            float lq[8];
            // chain segment: 8 exact steps; ballots deferred (off critical path)
#pragma unroll
            for (int t = 7; t >= 0; --t) {
                int ii = g8 * 8 + t;
                float th = __shfl_sync(0xffffffffu, thv, ii);
                float Ep = __shfl_up_sync(0xffffffffu, E, 1);
                if (lane == 0) Ep = 0.0f;
                float shifted = Ep + th;
                float Enew = logaddexpf32(E, shifted);
                lq[t] = shifted - Enew;       // logq, buffered
                E = Enew;
                g_B[((size_t)(base + ii) * BE + b) * KK + lane] = E;
            }
            // deferred mask generation: 8 independent expf+ballot, pipelined
#pragma unroll
            for (int t = 7; t >= 0; --t) {
                int ii = g8 * 8 + t;
                float u = __shfl_sync(0xffffffffu, uv, ii);
                float q = expf(fminf(lq[t], 0.0f));
                unsigned m = __ballot_sync(0xffffffffu, u < q);
                if (lane == 0) g_mask[(size_t)b * NN + base + ii] = m;
            }
        }
        thv = thv_next;
    }

    if (s < NSLICE - 1) {
        g_E[(size_t)b * KK + lane] = E;
    } else {
        float lz = __shfl_sync(0xffffffffu, E, 31);   // B[0][b][32] = logZ
        if (lane == 0) g_logZ[b] = lz;
    }
}

// ---------------- sampler chunk-function evaluation ----------------
// One warp per (b, chunk): lane holds hypothesis r_in = lane+1, walks 32 mask
// words, records resulting bits-word and r_out. Bit-exact with sequential sampler.
__device__ void samp_chunk(int xb, int band)
{
    int lane = threadIdx.x & 31;
    int item = xb * 4 + (threadIdx.x >> 5);   // 0..4095
    int b = item >> 4;
    int c = (112 - 16 * band) + (item & 15);  // chunk index 16..127 (bands 0..6)

    unsigned mv = g_mask[(size_t)b * NN + c * 32 + lane];  // coalesced
    unsigned r = (unsigned)(lane + 1);
    unsigned w = 0u;
#pragma unroll
    for (int ii = 0; ii < 32; ++ii) {
        unsigned m = __shfl_sync(0xffffffffu, mv, ii);
        unsigned incl = r ? ((m >> (r - 1u)) & 1u) : 0u;
        r -= incl;
        w |= incl << ii;
    }
    g_sampBits[((size_t)b * 128 + c) * 32 + lane] = w;
    g_sampMap[((size_t)b * 128 + c) * 32 + lane] = r;
}

// ---------------- sampler composition (hybrid): warp per b ----------------
// Chunks 0..15: masks only just arrived (slice-7 chain) — compute the chunk
// function inline, then select by the live state. Chunks 16..127: use tables.
// Per-step updates identical to the sequential sampler → bit-exact.
__device__ void comp_hybrid(int xb)
{
    const unsigned FULL = 0xffffffffu;
    int lane = threadIdx.x & 31;
    int b = xb * 4 + (threadIdx.x >> 5);
    const unsigned* mp = &g_sampMap[(size_t)b * 128 * 32];
    const unsigned* bp = &g_sampBits[(size_t)b * 128 * 32];

    unsigned r = KK;   // warp-uniform live state

    // chunks 0..15: inline hypothesis tables from fresh masks
    for (int c = 0; c < 16; ++c) {
        unsigned mv = g_mask[(size_t)b * NN + c * 32 + lane];
        unsigned rr = (unsigned)(lane + 1);
        unsigned w = 0u;
#pragma unroll
        for (int ii = 0; ii < 32; ++ii) {
            unsigned m = __shfl_sync(FULL, mv, ii);
            unsigned incl = rr ? ((m >> (rr - 1u)) & 1u) : 0u;
            rr -= incl;
            w |= incl << ii;
        }
        unsigned idx = r ? (r - 1u) : 0u;
        unsigned bits = __shfl_sync(FULL, w, idx);
        unsigned rn   = __shfl_sync(FULL, rr, idx);
        if (!r) { bits = 0u; rn = 0u; }
        if (lane == 0) g_bits[(size_t)b * 128 + c] = bits;
        r = rn;
    }

    // chunks 16..127: precomputed tables (loads independent of r → pipelined)
#pragma unroll 4
    for (int c = 16; c < 128; ++c) {
        unsigned mapv = mp[c * 32 + lane];
        unsigned bitv = bp[c * 32 + lane];
        unsigned idx = r ? (r - 1u) : 0u;
        unsigned bits = __shfl_sync(FULL, bitv, idx);
        unsigned rn   = __shfl_sync(FULL, mapv, idx);
        if (!r) { bits = 0u; rn = 0u; }
        if (lane == 0) g_bits[(size_t)b * 128 + c] = bits;
        r = rn;
    }
}

// ---------------- worker pieces (unchanged numerics) ----------------
__device__ void phaseA(const float* __restrict__ scores, int xb)
{
    int lane = threadIdx.x & 31;
    int wid = xb * 4 + (threadIdx.x >> 5);   // 0..8191
    int b = wid >> 5;
    int c = wid & 31;
    const int bz = b >> 1, e = b & 1;
    const float* thbase = scores + (size_t)bz * (NN * ENS) + e;

    float F = (lane == 0) ? 0.0f : NEGC;
    int base0 = c * CLEN;
    for (int blk = 0; blk < CLEN / 32; ++blk) {
        float thv = thbase[2 * (base0 + blk * 32 + lane)];
#pragma unroll 8
        for (int ii = 0; ii < 32; ++ii) {
            float th = __shfl_sync(0xffffffffu, thv, ii);
            float Fp = __shfl_up_sync(0xffffffffu, F, 1);
            if (lane == 0) Fp = NEGC;
            F = logaddexp_fast(F, Fp + th);
        }
    }
    g_CE[((size_t)b * NCHUNK + c) * KK + lane] = F;
}

__device__ void transpose_theta(const float* __restrict__ scores, int xb)
{
    int idx = (xb * 128 + threadIdx.x) * 4;
#pragma unroll
    for (int q = 0; q < 4; ++q, ++idx) {
        int b = idx & (BE - 1);
        int i = idx >> 8;
        g_T[idx] = scores[(size_t)(b >> 1) * (NN * ENS) + i * ENS + (b & 1)];
    }
}

__device__ void merge_chunks(int xb)
{
    int lane = threadIdx.x & 31;
    int b = xb * 4 + (threadIdx.x >> 5);

    float P = (lane == 0) ? 0.0f : NEGC;
    for (int c = 0; c < NCHUNK; ++c) {
        g_BD[((size_t)b * NCHUNK + c) * KK + lane] = P;  // exclusive prefix
        float L = g_CE[((size_t)b * NCHUNK + c) * KK + lane];
        float mx = NEGC;
#pragma unroll
        for (int m = 0; m < 32; ++m) {
            float Pm = __shfl_sync(0xffffffffu, P, m);
            float Lx = __shfl_sync(0xffffffffu, L, (lane - m) & 31);
            if (m <= lane) mx = fmaxf(mx, Pm + Lx);
        }
        float sum = 0.0f;
#pragma unroll
        for (int m = 0; m < 32; ++m) {
            float Pm = __shfl_sync(0xffffffffu, P, m);
            float Lx = __shfl_sync(0xffffffffu, L, (lane - m) & 31);
            if (m <= lane) sum += __expf(Pm + Lx - mx);
        }
        P = mx + __logf(sum);
    }
}

__device__ void phaseC_storeF(const float* __restrict__ scores, int xb)
{
    int lane = threadIdx.x & 31;
    int wid = xb * 4 + (threadIdx.x >> 5);
    int b = wid >> 5;
    int c = wid & 31;
    const int bz = b >> 1, e = b & 1;
    const float* thbase = scores + (size_t)bz * (NN * ENS) + e;

    float F = g_BD[((size_t)b * NCHUNK + c) * KK + lane];
    int base0 = c * CLEN;
    for (int blk = 0; blk < CLEN / 32; ++blk) {
        float thv = thbase[2 * (base0 + blk * 32 + lane)];
#pragma unroll 8
        for (int ii = 0; ii < 32; ++ii) {
            int i = base0 + blk * 32 + ii;
            g_F[((size_t)i * BE + b) * KK + lane] = F;
            float th = __shfl_sync(0xffffffffu, thv, ii);
            float Fp = __shfl_up_sync(0xffffffffu, F, 1);
            if (lane == 0) Fp = NEGC;
            F = logaddexp_fast(F, Fp + th);
        }
    }
}

__device__ void comb_band(int xb, int rowbase)
{
    int tid = xb * 128 + threadIdx.x;
    int b = tid & (BE - 1);
    int i = rowbase + (tid >> 8);

    const float4* Fr = reinterpret_cast<const float4*>(&g_F[((size_t)i * BE + b) * KK]);
    const float4* Br = reinterpret_cast<const float4*>(&g_B[((size_t)(i + 1) * BE + b) * KK]);

    float Fv[32], Bv[32];
#pragma unroll
    for (int q = 0; q < 8; ++q) {
        float4 f4 = Fr[q];
        Fv[4 * q + 0] = f4.x; Fv[4 * q + 1] = f4.y; Fv[4 * q + 2] = f4.z; Fv[4 * q + 3] = f4.w;
        float4 b4 = Br[q];
        Bv[4 * q + 0] = b4.x; Bv[4 * q + 1] = b4.y; Bv[4 * q + 2] = b4.z; Bv[4 * q + 3] = b4.w;
    }

    float comb[32];
#pragma unroll
    for (int j = 0; j < 32; ++j) {
        float bc = (j == 31) ? 0.0f : Bv[30 - j];   // B[i+1][31-j]; col 0 == 0
        comb[j] = Fv[j] + bc;
    }
    float mx = comb[0];
#pragma unroll
    for (int j = 1; j < 32; ++j) mx = fmaxf(mx, comb[j]);
    float sum = 0.0f;
#pragma unroll
    for (int j = 0; j < 32; ++j) sum += __expf(comb[j] - mx);

    g_S[(size_t)i * BE + b] = g_T[(size_t)i * BE + b] + mx + __logf(sum);
}

// ---------------- sliced fused kernel ----------------
__global__ void k_slice(const float* __restrict__ scores, int s)
{
    if (blockIdx.x < 64) {
        backward_slice(scores, s);
        return;
    }
    int xb = blockIdx.x - 64;
    if (s == 0) {
        if (xb < 2048) phaseA(scores, xb);
        else transpose_theta(scores, xb - 2048);
    } else if (s == 1) {
        if (xb < 64) merge_chunks(xb);
        else samp_chunk(xb - 64, 0);
    } else if (s == 2) {
        if (xb < 2048) phaseC_storeF(scores, xb);
        else samp_chunk(xb - 2048, 1);
    } else if (s == 3) {
        if (xb < 3072) comb_band(xb, 2560);          // rows [2560,4096)
        else samp_chunk(xb - 3072, 2);
    } else {
        // s=4..7: comb rows [4096-512s, 4096-512(s-1)) + sampler chunks band s-1
        if (xb < 1024) comb_band(xb, NN - SLEN * s);
        else samp_chunk(xb - 1024, s - 1);
    }
}

// ---------------- tail: last comb band + hybrid sampler composition ----------------
__global__ void k_tail()
{
    if (blockIdx.x < 1024) comb_band(blockIdx.x, 0);   // rows [0, 512)
    else comp_hybrid(blockIdx.x - 1024);               // 64 blocks, warp per b
}

// ---------------- finalize ----------------
__global__ void k_final(float* __restrict__ out)
{
    int tid = blockIdx.x * blockDim.x + threadIdx.x;  // 0 .. 2^20-1
    int bz = tid >> 13;
    int rem = tid & 8191;
    int n = rem >> 1;
    int e = rem & 1;
    int be = bz * ENS + e;
    float s = (float)((g_bits[(size_t)be * (NN / 32) + (n >> 5)] >> (n & 31)) & 1u);
    float m = __expf(g_S[(size_t)n * BE + be] - g_logZ[be]);
    out[tid] = (s - m) + m;
    out[HALF_OUT + tid] = m;
}

extern "C" void kernel_launch(void* const* d_in, const int* in_sizes, int n_in,
                              void* d_out, int out_size)
{
    const float* scores = (const float*)d_in[0];
    float* out = (float*)d_out;
    (void)in_sizes; (void)n_in; (void)out_size;

    k_slice<<<64 + 2048 + 2048, 128>>>(scores, 0);  // backward + phaseA + transpose
    k_slice<<<64 + 64 + 1024,   128>>>(scores, 1);  // backward + merge + sc b0
    k_slice<<<64 + 2048 + 1024, 128>>>(scores, 2);  // backward + phaseC + sc b1
    k_slice<<<64 + 3072 + 1024, 128>>>(scores, 3);  // backward + comb [2560,4096) + sc b2
    k_slice<<<64 + 1024 + 1024, 128>>>(scores, 4);  // backward + comb [2048,2560) + sc b3
    k_slice<<<64 + 1024 + 1024, 128>>>(scores, 5);  // backward + comb [1536,2048) + sc b4
    k_slice<<<64 + 1024 + 1024, 128>>>(scores, 6);  // backward + comb [1024,1536) + sc b5
    k_slice<<<64 + 1024 + 1024, 128>>>(scores, 7);  // backward + comb [512,1024)  + sc b6
    k_tail<<<1088, 128>>>();                        // comb [0,512) + hybrid comp
    k_final<<<2048, 512>>>(out);
}

// round 13
// speedup vs baseline: 2.7639x; 1.1105x over previous
#include <cuda_runtime.h>
#include <stdint.h>
#include <math.h>

// Problem constants (fixed shapes: scores (128, 4096, 2))
#define NN   4096
#define BSZ  128
#define ENS  2
#define BE   256           // BSZ*ENS
#define KK   32
#define NEGC (-1e30f)
#define HALF_OUT 1048576   // 128*4096*2
#define NCHUNK 32
#define CLEN   128         // NN / NCHUNK
#define NSLICE 8
#define SLEN   512         // NN / NSLICE
#define FULLM  0xffffffffu

// ---------------- scratch (static device memory) ----------------
__device__ float    g_B[(size_t)(NN + 1) * BE * KK]; // B[i][b][j-1]
__device__ unsigned g_mask[(size_t)BE * NN];         // inclusion masks [b*NN + i]
__device__ float    g_CE[(size_t)BE * NCHUNK * KK];  // chunk ESPs
__device__ float    g_BD[(size_t)BE * NCHUNK * KK];  // chunk boundary prefixes
__device__ float    g_M[(size_t)BE * NN];            // unnormalized marginals [b][i]
__device__ float    g_E[(size_t)BE * KK];            // backward state between slices
__device__ float    g_off[BE];                       // log e_31 (early normalizer)
__device__ float    g_logZ[BE];                      // exact log e_32
__device__ unsigned g_bits[(size_t)BE * (NN / 32)];  // sampled bits
// sampler chunk-function tables (chunks 16..127)
__device__ unsigned g_sampBits[(size_t)BE * 128 * 32];
__device__ unsigned g_sampMap[(size_t)BE * 128 * 32];

// ---------------- threefry2x32, key = (0, 42) ----------------
__device__ __forceinline__ uint32_t tf_bits(uint32_t lo)
{
    uint32_t x0 = 0u;
    uint32_t x1 = lo;
    const uint32_t ks0 = 0u, ks1 = 42u, ks2 = 0x1BD11BF0u;
    x0 += ks0; x1 += ks1;
#define TFR(r) { x0 += x1; x1 = (x1 << (r)) | (x1 >> (32 - (r))); x1 ^= x0; }
    TFR(13) TFR(15) TFR(26) TFR(6)   x0 += ks1; x1 += ks2 + 1u;
    TFR(17) TFR(29) TFR(16) TFR(24)  x0 += ks2; x1 += ks0 + 2u;
    TFR(13) TFR(15) TFR(26) TFR(6)   x0 += ks0; x1 += ks1 + 3u;
    TFR(17) TFR(29) TFR(16) TFR(24)  x0 += ks1; x1 += ks2 + 4u;
    TFR(13) TFR(15) TFR(26) TFR(6)   x0 += ks2; x1 += ks0 + 5u;
#undef TFR
    return x0 ^ x1;
}

// EXACT logaddexp (libdevice — bitwise path for sampling masks)
__device__ __forceinline__ float logaddexpf32(float x, float y)
{
    float d = x - y;
    return fmaxf(x, y) + log1pf(expf(-fabsf(d)));
}

// Fast logaddexp (marginals path, 1e-3 tolerance)
__device__ __forceinline__ float logaddexp_fast(float x, float y)
{
    float d = x - y;
    return fmaxf(x, y) + __logf(1.0f + __expf(-fabsf(d)));
}

// ---------------- backward slice (exact chain, DEFERRED ballots) ----------------
__device__ void backward_slice(const float* __restrict__ scores, int s)
{
    int lane = threadIdx.x & 31;
    int b = blockIdx.x * 4 + (threadIdx.x >> 5);
    const int bz = b >> 1, e = b & 1;
    const float* thbase = scores + (size_t)bz * (NN * ENS) + e;

    float E;
    if (s == 0) {
        E = NEGC;
        g_B[((size_t)NN * BE + b) * KK + lane] = NEGC;   // init row (i = NN)
    } else {
        E = g_E[(size_t)b * KK + lane];
    }

    int blk_hi = (NN / 32) - 16 * s;        // exclusive
    int blk_lo = blk_hi - 16;

    // prefetch theta for the first block of this slice
    float thv = thbase[2 * ((blk_hi - 1) * 32 + lane)];

    for (int blk = blk_hi - 1; blk >= blk_lo; --blk) {
        int base = blk * 32;
        float thv_next = (blk > blk_lo) ? thbase[2 * ((blk - 1) * 32 + lane)] : 0.0f;
        // inline threefry uniform (bit-identical to jax.random.uniform, index i*BE+b)
        uint32_t rb = tf_bits((uint32_t)((base + lane) * BE + b));
        float uv = fmaxf(__uint_as_float((rb >> 9) | 0x3f800000u) - 1.0f, 0.0f);

#pragma unroll
        for (int g8 = 3; g8 >= 0; --g8) {
            float lq[8];
            // chain segment: 8 exact steps; ballots deferred (off critical path)
#pragma unroll
            for (int t = 7; t >= 0; --t) {
                int ii = g8 * 8 + t;
                float th = __shfl_sync(FULLM, thv, ii);
                float Ep = __shfl_up_sync(FULLM, E, 1);
                if (lane == 0) Ep = 0.0f;
                float shifted = Ep + th;
                float Enew = logaddexpf32(E, shifted);
                lq[t] = shifted - Enew;       // logq, buffered
                E = Enew;
                g_B[((size_t)(base + ii) * BE + b) * KK + lane] = E;
            }
            // deferred mask generation: 8 independent expf+ballot, pipelined
#pragma unroll
            for (int t = 7; t >= 0; --t) {
                int ii = g8 * 8 + t;
                float u = __shfl_sync(FULLM, uv, ii);
                float q = expf(fminf(lq[t], 0.0f));
                unsigned m = __ballot_sync(FULLM, u < q);
                if (lane == 0) g_mask[(size_t)b * NN + base + ii] = m;
            }
        }
        thv = thv_next;
    }

    if (s < NSLICE - 1) {
        g_E[(size_t)b * KK + lane] = E;
    } else {
        float lz = __shfl_sync(FULLM, E, 31);   // B[0][b][32] = logZ
        if (lane == 0) g_logZ[b] = lz;
    }
}

// ---------------- sampler chunk-function evaluation (chunks 16..127) ----------------
__device__ void samp_chunk(int xb, int band)
{
    int lane = threadIdx.x & 31;
    int item = xb * 4 + (threadIdx.x >> 5);   // 0..4095
    int b = item >> 4;
    int c = (112 - 16 * band) + (item & 15);

    unsigned mv = g_mask[(size_t)b * NN + c * 32 + lane];  // coalesced
    unsigned r = (unsigned)(lane + 1);
    unsigned w = 0u;
#pragma unroll
    for (int ii = 0; ii < 32; ++ii) {
        unsigned m = __shfl_sync(FULLM, mv, ii);
        unsigned incl = r ? ((m >> (r - 1u)) & 1u) : 0u;
        r -= incl;
        w |= incl << ii;
    }
    g_sampBits[((size_t)b * 128 + c) * 32 + lane] = w;
    g_sampMap[((size_t)b * 128 + c) * 32 + lane] = r;
}

// ---------------- sampler composition (hybrid): warp per b ----------------
__device__ void comp_hybrid(int xb)
{
    int lane = threadIdx.x & 31;
    int b = xb * 4 + (threadIdx.x >> 5);
    const unsigned* mp = &g_sampMap[(size_t)b * 128 * 32];
    const unsigned* bp = &g_sampBits[(size_t)b * 128 * 32];

    unsigned r = KK;   // warp-uniform live state

    // chunks 0..15: inline hypothesis tables from fresh masks
    for (int c = 0; c < 16; ++c) {
        unsigned mv = g_mask[(size_t)b * NN + c * 32 + lane];
        unsigned rr = (unsigned)(lane + 1);
        unsigned w = 0u;
#pragma unroll
        for (int ii = 0; ii < 32; ++ii) {
            unsigned m = __shfl_sync(FULLM, mv, ii);
            unsigned incl = rr ? ((m >> (rr - 1u)) & 1u) : 0u;
            rr -= incl;
            w |= incl << ii;
        }
        unsigned idx = r ? (r - 1u) : 0u;
        unsigned bits = __shfl_sync(FULLM, w, idx);
        unsigned rn   = __shfl_sync(FULLM, rr, idx);
        if (!r) { bits = 0u; rn = 0u; }
        if (lane == 0) g_bits[(size_t)b * 128 + c] = bits;
        r = rn;
    }

    // chunks 16..127: precomputed tables
#pragma unroll 4
    for (int c = 16; c < 128; ++c) {
        unsigned mapv = mp[c * 32 + lane];
        unsigned bitv = bp[c * 32 + lane];
        unsigned idx = r ? (r - 1u) : 0u;
        unsigned bits = __shfl_sync(FULLM, bitv, idx);
        unsigned rn   = __shfl_sync(FULLM, mapv, idx);
        if (!r) { bits = 0u; rn = 0u; }
        if (lane == 0) g_bits[(size_t)b * 128 + c] = bits;
        r = rn;
    }
}

// ---------------- phase A: per-chunk local ESPs ----------------
__device__ void phaseA(const float* __restrict__ scores, int xb)
{
    int lane = threadIdx.x & 31;
    int wid = xb * 4 + (threadIdx.x >> 5);   // 0..8191
    int b = wid >> 5;
    int c = wid & 31;
    const int bz = b >> 1, e = b & 1;
    const float* thbase = scores + (size_t)bz * (NN * ENS) + e;

    float F = (lane == 0) ? 0.0f : NEGC;
    int base0 = c * CLEN;
    for (int blk = 0; blk < CLEN / 32; ++blk) {
        float thv = thbase[2 * (base0 + blk * 32 + lane)];
#pragma unroll 8
        for (int ii = 0; ii < 32; ++ii) {
            float th = __shfl_sync(FULLM, thv, ii);
            float Fp = __shfl_up_sync(FULLM, F, 1);
            if (lane == 0) Fp = NEGC;
            F = logaddexp_fast(F, Fp + th);
        }
    }
    g_CE[((size_t)b * NCHUNK + c) * KK + lane] = F;
}

// ---------------- merge: chunk boundary prefixes + off ----------------
__device__ void merge_chunks(int xb)
{
    int lane = threadIdx.x & 31;
    int b = xb * 4 + (threadIdx.x >> 5);

    float P = (lane == 0) ? 0.0f : NEGC;
    for (int c = 0; c < NCHUNK; ++c) {
        g_BD[((size_t)b * NCHUNK + c) * KK + lane] = P;  // exclusive prefix
        float L = g_CE[((size_t)b * NCHUNK + c) * KK + lane];
        float mx = NEGC;
#pragma unroll
        for (int m = 0; m < 32; ++m) {
            float Pm = __shfl_sync(FULLM, P, m);
            float Lx = __shfl_sync(FULLM, L, (lane - m) & 31);
            if (m <= lane) mx = fmaxf(mx, Pm + Lx);
        }
        float sum = 0.0f;
#pragma unroll
        for (int m = 0; m < 32; ++m) {
            float Pm = __shfl_sync(FULLM, P, m);
            float Lx = __shfl_sync(FULLM, L, (lane - m) & 31);
            if (m <= lane) sum += __expf(Pm + Lx - mx);
        }
        P = mx + __logf(sum);
    }
    // lane 31 holds log e_31 of the full set — early normalization offset
    if (lane == 31) g_off[b] = P;
}

// ---------------- fused phaseC + comb (no g_F materialization) ----------------
// Warp per (b, c). Rescans the chunk from its boundary prefix; at each step i,
// drops term exp(F[i][j] + B[i+1][31-j] + th_i - off) into a smem tile; every
// 32 steps lane l sums row l -> unnormalized marginal for row base+l.
__device__ void phaseC_comb(const float* __restrict__ scores, int item,
                            int cbase, int ccnt, float* tile)
{
    int lane = threadIdx.x & 31;
    int b = item / ccnt;
    int c = cbase + (item % ccnt);
    const int bz = b >> 1, e = b & 1;
    const float* thbase = scores + (size_t)bz * (NN * ENS) + e;

    float F = g_BD[((size_t)b * NCHUNK + c) * KK + lane];   // lane j holds log e_j
    float off = g_off[b];
    int base0 = c * CLEN;

    for (int blk = 0; blk < CLEN / 32; ++blk) {
        int base = base0 + blk * 32;
        float thv = thbase[2 * (base + lane)];
#pragma unroll 8
        for (int ii = 0; ii < 32; ++ii) {
            int i = base + ii;
            float Bv = g_B[((size_t)(i + 1) * BE + b) * KK + lane];  // col lane+1
            float th = __shfl_sync(FULLM, thv, ii);
            float Brev = __shfl_sync(FULLM, Bv, (30 - lane) & 31);   // col 31-lane
            if (lane == 31) Brev = 0.0f;                             // col 0 == 0
            tile[ii * 33 + lane] = __expf(F + Brev + (th - off));
            float Fp = __shfl_up_sync(FULLM, F, 1);
            if (lane == 0) Fp = NEGC;
            F = logaddexp_fast(F, Fp + th);
        }
        __syncwarp();
        // lane l sums tile row l (j = 0..31) -> marginal numerator for i = base+l
        const float* row = tile + lane * 33;
        float sum = 0.0f;
#pragma unroll
        for (int j = 0; j < 32; ++j) sum += row[j];
        g_M[(size_t)b * NN + base + lane] = sum;
        __syncwarp();
    }
}

// ---------------- sliced fused kernel ----------------
__global__ void k_slice(const float* __restrict__ scores, int s)
{
    __shared__ float s_tile[4][32 * 33];   // 16.9KB; only phaseC_comb uses it

    if (blockIdx.x < 64) {
        backward_slice(scores, s);
        return;
    }
    int xb = blockIdx.x - 64;
    float* tile = &s_tile[threadIdx.x >> 5][0];

    if (s == 0) {
        phaseA(scores, xb);                               // 2048 blocks
    } else if (s == 1) {
        if (xb < 64) merge_chunks(xb);
        else samp_chunk(xb - 64, 0);                      // 1024 blocks
    } else if (s == 2) {
        if (xb < 512) phaseC_comb(scores, xb * 4 + (threadIdx.x >> 5), 24, 8, tile);
        else samp_chunk(xb - 512, 1);
    } else {
        // s = 3..7: phaseC_comb chunks [32-4s, 32-4s+4) + sampler band s-1
        if (xb < 256) phaseC_comb(scores, xb * 4 + (threadIdx.x >> 5), 32 - 4 * s, 4, tile);
        else samp_chunk(xb - 256, s - 1);
    }
}

// ---------------- tail: last phaseC_comb band + hybrid composition ----------------
__global__ void k_tail(const float* __restrict__ scores)
{
    __shared__ float s_tile[4][32 * 33];
    if (blockIdx.x < 256) {
        phaseC_comb(scores, blockIdx.x * 4 + (threadIdx.x >> 5), 0, 4,
                    &s_tile[threadIdx.x >> 5][0]);
    } else {
        comp_hybrid(blockIdx.x - 256);   // 64 blocks, warp per b
    }
}

// ---------------- finalize ----------------
__global__ void k_final(float* __restrict__ out)
{
    int tid = blockIdx.x * blockDim.x + threadIdx.x;  // 0 .. 2^20-1
    int bz = tid >> 13;
    int rem = tid & 8191;
    int n = rem >> 1;
    int e = rem & 1;
    int be = bz * ENS + e;
    float s = (float)((g_bits[(size_t)be * (NN / 32) + (n >> 5)] >> (n & 31)) & 1u);
    float m = g_M[(size_t)be * NN + n] * __expf(g_off[be] - g_logZ[be]);
    out[tid] = (s - m) + m;
    out[HALF_OUT + tid] = m;
}

extern "C" void kernel_launch(void* const* d_in, const int* in_sizes, int n_in,
                              void* d_out, int out_size)
{
    const float* scores = (const float*)d_in[0];
    float* out = (float*)d_out;
    (void)in_sizes; (void)n_in; (void)out_size;

    k_slice<<<64 + 2048,       128>>>(scores, 0);  // backward + phaseA
    k_slice<<<64 + 64 + 1024,  128>>>(scores, 1);  // backward + merge + sc b0
    k_slice<<<64 + 512 + 1024, 128>>>(scores, 2);  // backward + PC c24-31 + sc b1
    k_slice<<<64 + 256 + 1024, 128>>>(scores, 3);  // backward + PC c20-23 + sc b2
    k_slice<<<64 + 256 + 1024, 128>>>(scores, 4);  // backward + PC c16-19 + sc b3
    k_slice<<<64 + 256 + 1024, 128>>>(scores, 5);  // backward + PC c12-15 + sc b4
    k_slice<<<64 + 256 + 1024, 128>>>(scores, 6);  // backward + PC c8-11  + sc b5
    k_slice<<<64 + 256 + 1024, 128>>>(scores, 7);  // backward + PC c4-7   + sc b6
    k_tail<<<320, 128>>>(scores);                  // PC c0-3 + hybrid comp
    k_final<<<2048, 512>>>(out);
}